// round 9
// baseline (speedup 1.0000x reference)
#include <cuda_runtime.h>
#include <cuda_fp16.h>
#include <mma.h>
#include <math.h>

using namespace nvcuda;

#define TT    2048
#define HD    2048
#define ID    1024
#define NEXP  32
#define NEZ   64
#define TOPKK 8
#define CAPE  1024
#define NSLOT (TT * TOPKK)

// ---------------- scratch (static device allocations) ----------------
__device__ float   g_logits[(size_t)TT * NEZ];
__device__ int     g_slot_eid[NSLOT];
__device__ float   g_slot_w[NSLOT];
__device__ int     g_count[NEXP];
__device__ int     g_tok[NEXP * CAPE];
__device__ float   g_wt[NEXP * CAPE];
__device__ __half2 g_act[(size_t)NEXP * CAPE * ID];   // (hi,lo) packed, 128 MB

union H8 { __half h[8]; uint4 u; };

__device__ __forceinline__ void split8(const float* f, uint4* uh, uint4* ul) {
    H8 hh, ll;
#pragma unroll
    for (int i = 0; i < 8; i++) {
        __half h = __float2half_rn(f[i]);
        hh.h[i] = h;
        ll.h[i] = __float2half_rn(f[i] - __half2float(h));
    }
    *uh = hh.u; *ul = ll.u;
}
__device__ __forceinline__ uint4 hi8(const float* f) {
    H8 hh;
#pragma unroll
    for (int i = 0; i < 8; i++) hh.h[i] = __float2half_rn(f[i]);
    return hh.u;
}

// ---------------- kernel 1: router logits, near-exact fp32 (Kahan) ----------
__global__ __launch_bounds__(256) void router_kernel(const float* __restrict__ x,
                                                     const float* __restrict__ wcls) {
    __shared__ float sx[HD];
    const int t = blockIdx.x;
    for (int i = threadIdx.x; i < HD; i += 256)
        sx[i] = x[(size_t)t * HD + i];
    __syncthreads();

    const int warp = threadIdx.x >> 5;
    const int lane = threadIdx.x & 31;
    for (int e = warp; e < NEZ; e += 8) {
        const float* w = wcls + (size_t)e * HD;
        float s = 0.f, comp = 0.f;
        for (int k = lane; k < HD; k += 32) {
            float p  = __fmul_rn(sx[k], w[k]);
            float y  = __fsub_rn(p, comp);
            float t2 = __fadd_rn(s, y);
            comp     = __fsub_rn(__fsub_rn(t2, s), y);
            s = t2;
        }
#pragma unroll
        for (int off = 16; off; off >>= 1)
            s = __fadd_rn(s, __shfl_xor_sync(0xffffffffu, s, off));
        if (lane == 0) g_logits[(size_t)t * NEZ + e] = s;
    }
}

// ---------------- kernel 2: softmax + top-8, write per-slot tables ----------
__global__ void route_kernel(const float* __restrict__ bias) {
    const int t = blockIdx.x * blockDim.x + threadIdx.x;
    if (t >= TT) return;

    const float* lg = g_logits + (size_t)t * NEZ;
    float sc[NEZ];
    float m = -1e30f;
#pragma unroll
    for (int j = 0; j < NEZ; j++) m = fmaxf(m, lg[j]);
    float s = 0.f;
#pragma unroll
    for (int j = 0; j < NEZ; j++) { sc[j] = expf(lg[j] - m); s += sc[j]; }
    const float invs = 1.f / s;
    float sel[NEZ];
#pragma unroll
    for (int j = 0; j < NEZ; j++) { sc[j] *= invs; sel[j] = sc[j] + bias[j]; }

    int   idx[TOPKK];
    float w[TOPKK];
    float wsum = 0.f;
#pragma unroll
    for (int k = 0; k < TOPKK; k++) {
        float best = -1e30f; int bj = 0;
        for (int j = 0; j < NEZ; j++)
            if (sel[j] > best) { best = sel[j]; bj = j; }
        idx[k] = bj;
        w[k]   = sc[bj];
        wsum  += sc[bj];
        sel[bj] = -1e30f;
    }

    const float inv = 1.5f / (wsum + 1e-20f);
    float zsum = 0.f;
#pragma unroll
    for (int k = 0; k < TOPKK; k++)
        if (idx[k] >= NEXP) zsum += w[k] * inv;
    const float zscale = 1.f + zsum;

#pragma unroll
    for (int k = 0; k < TOPKK; k++) {
        int e = idx[k];
        int slot = t * TOPKK + k;
        if (e < NEXP) {
            g_slot_eid[slot] = e;
            g_slot_w[slot]   = w[k] * inv * zscale;
        } else {
            g_slot_eid[slot] = -1;
            g_slot_w[slot]   = 0.f;
        }
    }
}

// ---------------- kernel 2b: deterministic dispatch (reference drop rule) ----
__global__ __launch_bounds__(1024) void dispatch_kernel() {
    const int e = blockIdx.x;
    __shared__ int warp_cnt[32];
    __shared__ int running_s;
    if (threadIdx.x == 0) running_s = 0;
    __syncthreads();

    const int lane = threadIdx.x & 31;
    const int warp = threadIdx.x >> 5;

    for (int base = 0; base < NSLOT; base += 1024) {
        const int i = base + threadIdx.x;
        const bool f = (g_slot_eid[i] == e);
        const unsigned mball = __ballot_sync(0xffffffffu, f);
        const int wprefix = __popc(mball & ((1u << lane) - 1u));
        if (lane == 0) warp_cnt[warp] = __popc(mball);
        __syncthreads();

        int woff = 0, tot = 0;
#pragma unroll
        for (int w2 = 0; w2 < 32; w2++) {
            int c = warp_cnt[w2];
            if (w2 < warp) woff += c;
            tot += c;
        }
        const int run0 = running_s;
        if (f) {
            int pos = run0 + woff + wprefix;
            if (pos < CAPE) {
                g_tok[e * CAPE + pos] = i / TOPKK;
                g_wt [e * CAPE + pos] = g_slot_w[i];
            }
        }
        __syncthreads();
        if (threadIdx.x == 0) running_s = run0 + tot;
        __syncthreads();
    }
    if (threadIdx.x == 0) g_count[e] = running_s;
}

// ---------------- kernel 3: grouped GEMM1 + SwiGLU (pipelined, 2-term) ------
// A (tokens) split hi/lo exactly; B (weights) fp16-hi only.
#define G1_SAH 0
#define G1_SAL 10240
#define G1_SBG 20480
#define G1_SBU 29696
#define G1_SMEM 38912

__global__ __launch_bounds__(256, 2) void gemm1_kernel(const float* __restrict__ x,
                                                       const float* __restrict__ wgu) {
    const int e     = blockIdx.z;
    const int n_eff = min(g_count[e], CAPE);
    const int m0    = blockIdx.y * 64;
    if (m0 >= n_eff) return;
    const int n0 = blockIdx.x * 64;

    __shared__ __align__(16) unsigned char smem_raw[G1_SMEM];
    __shared__ int stok[64];
    typedef __half (*A_t)[64][40];
    typedef __half (*B_t)[32][72];
    A_t sAh = (A_t)(smem_raw + G1_SAH);
    A_t sAl = (A_t)(smem_raw + G1_SAL);
    B_t sBg = (B_t)(smem_raw + G1_SBG);
    B_t sBu = (B_t)(smem_raw + G1_SBU);

    const int tid = threadIdx.x;
    if (tid < 64) {
        int r = m0 + tid;
        stok[tid] = (r < n_eff) ? g_tok[e * CAPE + r] : -1;
    }
    __syncthreads();

    const float* wg = wgu + (size_t)e * HD * (2 * ID);
    const int warp = tid >> 5;
    const int wm = warp & 1, wn = warp >> 1;

    // loader mappings
    const int a_r = tid >> 2;
    const int a_c = (tid & 3) << 3;                 // 0,8,16,24
    const int atok = stok[a_r];
    const float* aptr = (atok >= 0) ? (x + (size_t)atok * HD + a_c) : nullptr;

    const int b_m = tid >> 7;                        // 0=gate, 1=up
    const int b_r = (tid & 127) >> 2;                // 0..31
    const int b_c = (tid & 3) << 4;                  // 0,16,32,48
    const float* bptr = wg + (size_t)b_r * (2 * ID) + b_m * ID + n0 + b_c;
    B_t sBdst = b_m ? sBu : sBg;

    wmma::fragment<wmma::accumulator, 16, 16, 16, float> cg[2], cu[2];
#pragma unroll
    for (int i = 0; i < 2; i++) { wmma::fill_fragment(cg[i], 0.f); wmma::fill_fragment(cu[i], 0.f); }

    float4 ra0, ra1, rb0, rb1, rb2, rb3;
    auto load_regs = [&](int k) {
        if (aptr) { ra0 = *(const float4*)(aptr + k); ra1 = *(const float4*)(aptr + k + 4); }
        else      { ra0 = make_float4(0.f,0.f,0.f,0.f); ra1 = ra0; }
        const float* bp = bptr + (size_t)k * (2 * ID);
        rb0 = *(const float4*)(bp);     rb1 = *(const float4*)(bp + 4);
        rb2 = *(const float4*)(bp + 8); rb3 = *(const float4*)(bp + 12);
    };
    auto store_stage = [&](int s) {
        float fa[8] = {ra0.x, ra0.y, ra0.z, ra0.w, ra1.x, ra1.y, ra1.z, ra1.w};
        uint4 uh, ul; split8(fa, &uh, &ul);
        *(uint4*)&sAh[s][a_r][a_c] = uh;
        *(uint4*)&sAl[s][a_r][a_c] = ul;
        float fb0[8] = {rb0.x, rb0.y, rb0.z, rb0.w, rb1.x, rb1.y, rb1.z, rb1.w};
        float fb1[8] = {rb2.x, rb2.y, rb2.z, rb2.w, rb3.x, rb3.y, rb3.z, rb3.w};
        *(uint4*)&sBdst[s][b_r][b_c]     = hi8(fb0);
        *(uint4*)&sBdst[s][b_r][b_c + 8] = hi8(fb1);
    };

    load_regs(0);
    store_stage(0);
    __syncthreads();

    const int NK = HD / 32;
    for (int ks = 0; ks < NK; ks++) {
        const int cur = ks & 1;
        const bool hasnext = (ks + 1 < NK);
        if (hasnext) load_regs((ks + 1) * 32);
#pragma unroll
        for (int sub = 0; sub < 2; sub++) {
            wmma::fragment<wmma::matrix_a, 16, 16, 16, __half, wmma::row_major> a0h, a1h, a0l, a1l;
            wmma::load_matrix_sync(a0h, &sAh[cur][wm * 32][sub * 16], 40);
            wmma::load_matrix_sync(a1h, &sAh[cur][wm * 32 + 16][sub * 16], 40);
            wmma::load_matrix_sync(a0l, &sAl[cur][wm * 32][sub * 16], 40);
            wmma::load_matrix_sync(a1l, &sAl[cur][wm * 32 + 16][sub * 16], 40);
            wmma::fragment<wmma::matrix_b, 16, 16, 16, __half, wmma::row_major> b;
            wmma::load_matrix_sync(b, &sBg[cur][sub * 16][wn * 16], 72);
            wmma::mma_sync(cg[0], a0h, b, cg[0]);
            wmma::mma_sync(cg[1], a1h, b, cg[1]);
            wmma::mma_sync(cg[0], a0l, b, cg[0]);
            wmma::mma_sync(cg[1], a1l, b, cg[1]);
            wmma::load_matrix_sync(b, &sBu[cur][sub * 16][wn * 16], 72);
            wmma::mma_sync(cu[0], a0h, b, cu[0]);
            wmma::mma_sync(cu[1], a1h, b, cu[1]);
            wmma::mma_sync(cu[0], a0l, b, cu[0]);
            wmma::mma_sync(cu[1], a1l, b, cu[1]);
        }
        if (hasnext) store_stage(cur ^ 1);
        __syncthreads();
    }

    // ---- epilogue (sOut aliases pipeline smem; safe after final sync) ----
    float (*sOut)[68] = (float(*)[68])smem_raw;
    const int lane = tid & 31;
    float gv[16];
#pragma unroll
    for (int i = 0; i < 2; i++)
        wmma::store_matrix_sync(&sOut[wm * 32 + i * 16][wn * 16], cg[i], 68, wmma::mem_row_major);
    __syncwarp();
#pragma unroll
    for (int it = 0; it < 16; it++) {
        int i = it * 32 + lane;
        gv[it] = sOut[wm * 32 + (i >> 4)][wn * 16 + (i & 15)];
    }
    __syncwarp();
#pragma unroll
    for (int i = 0; i < 2; i++)
        wmma::store_matrix_sync(&sOut[wm * 32 + i * 16][wn * 16], cu[i], 68, wmma::mem_row_major);
    __syncwarp();
#pragma unroll
    for (int it = 0; it < 16; it++) {
        int i = it * 32 + lane;
        int r = wm * 32 + (i >> 4);
        int c = wn * 16 + (i & 15);
        int grow = m0 + r;
        if (grow < n_eff) {
            float g = gv[it];
            float u = sOut[r][c];
            float act = g / (1.f + expf(-g)) * u;
            __half hh = __float2half_rn(act);
            __half hl = __float2half_rn(act - __half2float(hh));
            g_act[((size_t)e * CAPE + grow) * ID + n0 + c] = __halves2half2(hh, hl);
        }
    }
}

// ---------------- kernel 4: grouped GEMM2 + weighted scatter (pipelined) ----
#define G2_SAH 0
#define G2_SAL 10240
#define G2_SB  20480
#define G2_SMEM 29696

__global__ __launch_bounds__(256, 2) void gemm2_kernel(const float* __restrict__ wdown,
                                                       float* __restrict__ out) {
    const int e     = blockIdx.z;
    const int n_eff = min(g_count[e], CAPE);
    const int m0    = blockIdx.y * 64;
    if (m0 >= n_eff) return;
    const int n0 = blockIdx.x * 64;

    __shared__ __align__(16) unsigned char smem_raw[G2_SMEM];
    __shared__ int   stok[64];
    __shared__ float swt[64];
    typedef __half (*A_t)[64][40];
    typedef __half (*B_t)[32][72];
    A_t sAh = (A_t)(smem_raw + G2_SAH);
    A_t sAl = (A_t)(smem_raw + G2_SAL);
    B_t sB  = (B_t)(smem_raw + G2_SB);

    const int tid = threadIdx.x;
    if (tid < 64) {
        int r = m0 + tid;
        if (r < n_eff) { stok[tid] = g_tok[e * CAPE + r]; swt[tid] = g_wt[e * CAPE + r]; }
        else           { stok[tid] = -1;                  swt[tid] = 0.f; }
    }
    __syncthreads();

    const int warp = tid >> 5;
    const int wm = warp & 1, wn = warp >> 1;

    const int a_r = tid >> 2;
    const int a_c = (tid & 3) << 3;                 // half2 units: 0,8,16,24
    const bool avalid = (m0 + a_r) < n_eff;
    const __half2* ap = g_act + ((size_t)e * CAPE + m0 + a_r) * ID + a_c;

    const int b_r = tid >> 3;                        // 0..31
    const int b_c = (tid & 7) << 3;                  // 0..56 step 8
    const float* bp0 = wdown + (size_t)e * ID * HD + (size_t)b_r * HD + n0 + b_c;

    wmma::fragment<wmma::accumulator, 16, 16, 16, float> c[2];
    wmma::fill_fragment(c[0], 0.f);
    wmma::fill_fragment(c[1], 0.f);

    uint4 va0, va1; float4 rb0, rb1;
    auto load_regs = [&](int k) {
        if (avalid) { va0 = *(const uint4*)(ap + k); va1 = *(const uint4*)(ap + k + 4); }
        else        { va0 = make_uint4(0,0,0,0); va1 = va0; }
        const float* bp = bp0 + (size_t)k * HD;
        rb0 = *(const float4*)(bp); rb1 = *(const float4*)(bp + 4);
    };
    auto store_stage = [&](int s) {
        uint4 uh, ul;
        uh.x = __byte_perm(va0.x, va0.y, 0x5410); ul.x = __byte_perm(va0.x, va0.y, 0x7632);
        uh.y = __byte_perm(va0.z, va0.w, 0x5410); ul.y = __byte_perm(va0.z, va0.w, 0x7632);
        uh.z = __byte_perm(va1.x, va1.y, 0x5410); ul.z = __byte_perm(va1.x, va1.y, 0x7632);
        uh.w = __byte_perm(va1.z, va1.w, 0x5410); ul.w = __byte_perm(va1.z, va1.w, 0x7632);
        *(uint4*)&sAh[s][a_r][a_c] = uh;
        *(uint4*)&sAl[s][a_r][a_c] = ul;
        float fb[8] = {rb0.x, rb0.y, rb0.z, rb0.w, rb1.x, rb1.y, rb1.z, rb1.w};
        *(uint4*)&sB[s][b_r][b_c] = hi8(fb);
    };

    load_regs(0);
    store_stage(0);
    __syncthreads();

    const int NK = ID / 32;
    for (int ks = 0; ks < NK; ks++) {
        const int cur = ks & 1;
        const bool hasnext = (ks + 1 < NK);
        if (hasnext) load_regs((ks + 1) * 32);
#pragma unroll
        for (int sub = 0; sub < 2; sub++) {
            wmma::fragment<wmma::matrix_a, 16, 16, 16, __half, wmma::row_major> a0h, a1h, a0l, a1l;
            wmma::load_matrix_sync(a0h, &sAh[cur][wm * 32][sub * 16], 40);
            wmma::load_matrix_sync(a1h, &sAh[cur][wm * 32 + 16][sub * 16], 40);
            wmma::load_matrix_sync(a0l, &sAl[cur][wm * 32][sub * 16], 40);
            wmma::load_matrix_sync(a1l, &sAl[cur][wm * 32 + 16][sub * 16], 40);
            wmma::fragment<wmma::matrix_b, 16, 16, 16, __half, wmma::row_major> b;
            wmma::load_matrix_sync(b, &sB[cur][sub * 16][wn * 16], 72);
            wmma::mma_sync(c[0], a0h, b, c[0]);
            wmma::mma_sync(c[1], a1h, b, c[1]);
            wmma::mma_sync(c[0], a0l, b, c[0]);
            wmma::mma_sync(c[1], a1l, b, c[1]);
        }
        if (hasnext) store_stage(cur ^ 1);
        __syncthreads();
    }

    float (*sOut)[68] = (float(*)[68])smem_raw;
#pragma unroll
    for (int i = 0; i < 2; i++)
        wmma::store_matrix_sync(&sOut[wm * 32 + i * 16][wn * 16], c[i], 68, wmma::mem_row_major);
    __syncwarp();

    const int lane = tid & 31;
    for (int i = lane; i < 32 * 16; i += 32) {
        int r  = wm * 32 + (i >> 4);
        int cc = wn * 16 + (i & 15);
        int t = stok[r];
        if (t >= 0)
            atomicAdd(&out[(size_t)t * HD + n0 + cc], sOut[r][cc] * swt[r]);
    }
}

// ---------------- launcher ----------------
extern "C" void kernel_launch(void* const* d_in, const int* in_sizes, int n_in,
                              void* d_out, int out_size) {
    (void)in_sizes; (void)n_in; (void)out_size;
    const float* x     = (const float*)d_in[0];
    const float* wcls  = (const float*)d_in[1];
    const float* bias  = (const float*)d_in[2];
    const float* wgu   = (const float*)d_in[3];
    const float* wdown = (const float*)d_in[4];
    float* out = (float*)d_out;

    cudaMemsetAsync(out, 0, (size_t)TT * HD * sizeof(float));
    router_kernel<<<TT, 256>>>(x, wcls);
    route_kernel<<<TT / 256, 256>>>(bias);
    dispatch_kernel<<<NEXP, 1024>>>();
    gemm1_kernel<<<dim3(ID / 64, CAPE / 64, NEXP), 256>>>(x, wgu);
    gemm2_kernel<<<dim3(HD / 64, CAPE / 64, NEXP), 256>>>(wdown, out);
}

// round 10
// speedup vs baseline: 1.0030x; 1.0030x over previous
#include <cuda_runtime.h>
#include <cuda_fp16.h>
#include <mma.h>
#include <math.h>

using namespace nvcuda;

#define TT    2048
#define HD    2048
#define ID    1024
#define NEXP  32
#define NEZ   64
#define TOPKK 8
#define CAPE  1024
#define NSLOT (TT * TOPKK)

// ---------------- scratch (static device allocations) ----------------
__device__ float   g_logits[(size_t)TT * NEZ];
__device__ int     g_slot_eid[NSLOT];
__device__ float   g_slot_w[NSLOT];
__device__ int     g_count[NEXP];
__device__ int     g_tok[NEXP * CAPE];
__device__ float   g_wt[NEXP * CAPE];
__device__ __half2 g_act[(size_t)NEXP * CAPE * ID];   // (hi,lo) packed, 128 MB

union H8 { __half h[8]; uint4 u; };

__device__ __forceinline__ void split8(const float* f, uint4* uh, uint4* ul) {
    H8 hh, ll;
#pragma unroll
    for (int i = 0; i < 8; i++) {
        __half h = __float2half_rn(f[i]);
        hh.h[i] = h;
        ll.h[i] = __float2half_rn(f[i] - __half2float(h));
    }
    *uh = hh.u; *ul = ll.u;
}
__device__ __forceinline__ uint4 hi8(const float* f) {
    H8 hh;
#pragma unroll
    for (int i = 0; i < 8; i++) hh.h[i] = __float2half_rn(f[i]);
    return hh.u;
}

// ---------------- kernel 1: router logits, near-exact fp32 (Kahan) ----------
__global__ __launch_bounds__(256) void router_kernel(const float* __restrict__ x,
                                                     const float* __restrict__ wcls) {
    __shared__ float sx[HD];
    const int t = blockIdx.x;
    for (int i = threadIdx.x; i < HD; i += 256)
        sx[i] = x[(size_t)t * HD + i];
    __syncthreads();

    const int warp = threadIdx.x >> 5;
    const int lane = threadIdx.x & 31;
    for (int e = warp; e < NEZ; e += 8) {
        const float* w = wcls + (size_t)e * HD;
        float s = 0.f, comp = 0.f;
        for (int k = lane; k < HD; k += 32) {
            float p  = __fmul_rn(sx[k], w[k]);
            float y  = __fsub_rn(p, comp);
            float t2 = __fadd_rn(s, y);
            comp     = __fsub_rn(__fsub_rn(t2, s), y);
            s = t2;
        }
#pragma unroll
        for (int off = 16; off; off >>= 1)
            s = __fadd_rn(s, __shfl_xor_sync(0xffffffffu, s, off));
        if (lane == 0) g_logits[(size_t)t * NEZ + e] = s;
    }
}

// ---------------- kernel 2: softmax + top-8, write per-slot tables ----------
__global__ void route_kernel(const float* __restrict__ bias) {
    const int t = blockIdx.x * blockDim.x + threadIdx.x;
    if (t >= TT) return;

    const float* lg = g_logits + (size_t)t * NEZ;
    float sc[NEZ];
    float m = -1e30f;
#pragma unroll
    for (int j = 0; j < NEZ; j++) m = fmaxf(m, lg[j]);
    float s = 0.f;
#pragma unroll
    for (int j = 0; j < NEZ; j++) { sc[j] = expf(lg[j] - m); s += sc[j]; }
    const float invs = 1.f / s;
    float sel[NEZ];
#pragma unroll
    for (int j = 0; j < NEZ; j++) { sc[j] *= invs; sel[j] = sc[j] + bias[j]; }

    int   idx[TOPKK];
    float w[TOPKK];
    float wsum = 0.f;
#pragma unroll
    for (int k = 0; k < TOPKK; k++) {
        float best = -1e30f; int bj = 0;
        for (int j = 0; j < NEZ; j++)
            if (sel[j] > best) { best = sel[j]; bj = j; }
        idx[k] = bj;
        w[k]   = sc[bj];
        wsum  += sc[bj];
        sel[bj] = -1e30f;
    }

    const float inv = 1.5f / (wsum + 1e-20f);
    float zsum = 0.f;
#pragma unroll
    for (int k = 0; k < TOPKK; k++)
        if (idx[k] >= NEXP) zsum += w[k] * inv;
    const float zscale = 1.f + zsum;

#pragma unroll
    for (int k = 0; k < TOPKK; k++) {
        int e = idx[k];
        int slot = t * TOPKK + k;
        if (e < NEXP) {
            g_slot_eid[slot] = e;
            g_slot_w[slot]   = w[k] * inv * zscale;
        } else {
            g_slot_eid[slot] = -1;
            g_slot_w[slot]   = 0.f;
        }
    }
}

// ---------------- kernel 2b: deterministic dispatch (reference drop rule) ----
__global__ __launch_bounds__(1024) void dispatch_kernel() {
    const int e = blockIdx.x;
    __shared__ int warp_cnt[32];
    __shared__ int running_s;
    if (threadIdx.x == 0) running_s = 0;
    __syncthreads();

    const int lane = threadIdx.x & 31;
    const int warp = threadIdx.x >> 5;

    for (int base = 0; base < NSLOT; base += 1024) {
        const int i = base + threadIdx.x;
        const bool f = (g_slot_eid[i] == e);
        const unsigned mball = __ballot_sync(0xffffffffu, f);
        const int wprefix = __popc(mball & ((1u << lane) - 1u));
        if (lane == 0) warp_cnt[warp] = __popc(mball);
        __syncthreads();

        int woff = 0, tot = 0;
#pragma unroll
        for (int w2 = 0; w2 < 32; w2++) {
            int c = warp_cnt[w2];
            if (w2 < warp) woff += c;
            tot += c;
        }
        const int run0 = running_s;
        if (f) {
            int pos = run0 + woff + wprefix;
            if (pos < CAPE) {
                g_tok[e * CAPE + pos] = i / TOPKK;
                g_wt [e * CAPE + pos] = g_slot_w[i];
            }
        }
        __syncthreads();
        if (threadIdx.x == 0) running_s = run0 + tot;
        __syncthreads();
    }
    if (threadIdx.x == 0) g_count[e] = running_s;
}

// ---------------- kernel 3: grouped GEMM1 + SwiGLU (pipelined, 2-term) ------
// A (tokens) split hi/lo exactly; B (weights) fp16-hi only.
#define G1_SAH 0
#define G1_SAL 10240
#define G1_SBG 20480
#define G1_SBU 29696
#define G1_SMEM 38912

__global__ __launch_bounds__(256, 2) void gemm1_kernel(const float* __restrict__ x,
                                                       const float* __restrict__ wgu) {
    const int e     = blockIdx.z;
    const int n_eff = min(g_count[e], CAPE);
    const int m0    = blockIdx.y * 64;
    if (m0 >= n_eff) return;
    const int n0 = blockIdx.x * 64;

    __shared__ __align__(16) unsigned char smem_raw[G1_SMEM];
    __shared__ int stok[64];
    typedef __half (*A_t)[64][40];
    typedef __half (*B_t)[32][72];
    A_t sAh = (A_t)(smem_raw + G1_SAH);
    A_t sAl = (A_t)(smem_raw + G1_SAL);
    B_t sBg = (B_t)(smem_raw + G1_SBG);
    B_t sBu = (B_t)(smem_raw + G1_SBU);

    const int tid = threadIdx.x;
    if (tid < 64) {
        int r = m0 + tid;
        stok[tid] = (r < n_eff) ? g_tok[e * CAPE + r] : -1;
    }
    __syncthreads();

    const float* wg = wgu + (size_t)e * HD * (2 * ID);
    const int warp = tid >> 5;
    const int wm = warp & 1, wn = warp >> 1;

    // loader mappings
    const int a_r = tid >> 2;
    const int a_c = (tid & 3) << 3;                 // 0,8,16,24
    const int atok = stok[a_r];
    const float* aptr = (atok >= 0) ? (x + (size_t)atok * HD + a_c) : nullptr;

    const int b_m = tid >> 7;                        // 0=gate, 1=up
    const int b_r = (tid & 127) >> 2;                // 0..31
    const int b_c = (tid & 3) << 4;                  // 0,16,32,48
    const float* bptr = wg + (size_t)b_r * (2 * ID) + b_m * ID + n0 + b_c;
    B_t sBdst = b_m ? sBu : sBg;

    wmma::fragment<wmma::accumulator, 16, 16, 16, float> cg[2], cu[2];
#pragma unroll
    for (int i = 0; i < 2; i++) { wmma::fill_fragment(cg[i], 0.f); wmma::fill_fragment(cu[i], 0.f); }

    float4 ra0, ra1, rb0, rb1, rb2, rb3;
    auto load_regs = [&](int k) {
        if (aptr) { ra0 = *(const float4*)(aptr + k); ra1 = *(const float4*)(aptr + k + 4); }
        else      { ra0 = make_float4(0.f,0.f,0.f,0.f); ra1 = ra0; }
        const float* bp = bptr + (size_t)k * (2 * ID);
        rb0 = *(const float4*)(bp);     rb1 = *(const float4*)(bp + 4);
        rb2 = *(const float4*)(bp + 8); rb3 = *(const float4*)(bp + 12);
    };
    auto store_stage = [&](int s) {
        float fa[8] = {ra0.x, ra0.y, ra0.z, ra0.w, ra1.x, ra1.y, ra1.z, ra1.w};
        uint4 uh, ul; split8(fa, &uh, &ul);
        *(uint4*)&sAh[s][a_r][a_c] = uh;
        *(uint4*)&sAl[s][a_r][a_c] = ul;
        float fb0[8] = {rb0.x, rb0.y, rb0.z, rb0.w, rb1.x, rb1.y, rb1.z, rb1.w};
        float fb1[8] = {rb2.x, rb2.y, rb2.z, rb2.w, rb3.x, rb3.y, rb3.z, rb3.w};
        *(uint4*)&sBdst[s][b_r][b_c]     = hi8(fb0);
        *(uint4*)&sBdst[s][b_r][b_c + 8] = hi8(fb1);
    };

    load_regs(0);
    store_stage(0);
    __syncthreads();

    const int NK = HD / 32;
    for (int ks = 0; ks < NK; ks++) {
        const int cur = ks & 1;
        const bool hasnext = (ks + 1 < NK);
        if (hasnext) load_regs((ks + 1) * 32);
#pragma unroll
        for (int sub = 0; sub < 2; sub++) {
            wmma::fragment<wmma::matrix_a, 16, 16, 16, __half, wmma::row_major> a0h, a1h, a0l, a1l;
            wmma::load_matrix_sync(a0h, &sAh[cur][wm * 32][sub * 16], 40);
            wmma::load_matrix_sync(a1h, &sAh[cur][wm * 32 + 16][sub * 16], 40);
            wmma::load_matrix_sync(a0l, &sAl[cur][wm * 32][sub * 16], 40);
            wmma::load_matrix_sync(a1l, &sAl[cur][wm * 32 + 16][sub * 16], 40);
            wmma::fragment<wmma::matrix_b, 16, 16, 16, __half, wmma::row_major> b;
            wmma::load_matrix_sync(b, &sBg[cur][sub * 16][wn * 16], 72);
            wmma::mma_sync(cg[0], a0h, b, cg[0]);
            wmma::mma_sync(cg[1], a1h, b, cg[1]);
            wmma::mma_sync(cg[0], a0l, b, cg[0]);
            wmma::mma_sync(cg[1], a1l, b, cg[1]);
            wmma::load_matrix_sync(b, &sBu[cur][sub * 16][wn * 16], 72);
            wmma::mma_sync(cu[0], a0h, b, cu[0]);
            wmma::mma_sync(cu[1], a1h, b, cu[1]);
            wmma::mma_sync(cu[0], a0l, b, cu[0]);
            wmma::mma_sync(cu[1], a1l, b, cu[1]);
        }
        if (hasnext) store_stage(cur ^ 1);
        __syncthreads();
    }

    // ---- epilogue (sOut aliases pipeline smem; safe after final sync) ----
    float (*sOut)[68] = (float(*)[68])smem_raw;
    const int lane = tid & 31;
    float gv[16];
#pragma unroll
    for (int i = 0; i < 2; i++)
        wmma::store_matrix_sync(&sOut[wm * 32 + i * 16][wn * 16], cg[i], 68, wmma::mem_row_major);
    __syncwarp();
#pragma unroll
    for (int it = 0; it < 16; it++) {
        int i = it * 32 + lane;
        gv[it] = sOut[wm * 32 + (i >> 4)][wn * 16 + (i & 15)];
    }
    __syncwarp();
#pragma unroll
    for (int i = 0; i < 2; i++)
        wmma::store_matrix_sync(&sOut[wm * 32 + i * 16][wn * 16], cu[i], 68, wmma::mem_row_major);
    __syncwarp();
#pragma unroll
    for (int it = 0; it < 16; it++) {
        int i = it * 32 + lane;
        int r = wm * 32 + (i >> 4);
        int c = wn * 16 + (i & 15);
        int grow = m0 + r;
        if (grow < n_eff) {
            float g = gv[it];
            float u = sOut[r][c];
            float act = g / (1.f + expf(-g)) * u;
            __half hh = __float2half_rn(act);
            __half hl = __float2half_rn(act - __half2float(hh));
            g_act[((size_t)e * CAPE + grow) * ID + n0 + c] = __halves2half2(hh, hl);
        }
    }
}

// ---------------- kernel 4: grouped GEMM2 + weighted scatter (pipelined) ----
#define G2_SAH 0
#define G2_SAL 10240
#define G2_SB  20480
#define G2_SMEM 29696

__global__ __launch_bounds__(256, 2) void gemm2_kernel(const float* __restrict__ wdown,
                                                       float* __restrict__ out) {
    const int e     = blockIdx.z;
    const int n_eff = min(g_count[e], CAPE);
    const int m0    = blockIdx.y * 64;
    if (m0 >= n_eff) return;
    const int n0 = blockIdx.x * 64;

    __shared__ __align__(16) unsigned char smem_raw[G2_SMEM];
    __shared__ int   stok[64];
    __shared__ float swt[64];
    typedef __half (*A_t)[64][40];
    typedef __half (*B_t)[32][72];
    A_t sAh = (A_t)(smem_raw + G2_SAH);
    A_t sAl = (A_t)(smem_raw + G2_SAL);
    B_t sB  = (B_t)(smem_raw + G2_SB);

    const int tid = threadIdx.x;
    if (tid < 64) {
        int r = m0 + tid;
        if (r < n_eff) { stok[tid] = g_tok[e * CAPE + r]; swt[tid] = g_wt[e * CAPE + r]; }
        else           { stok[tid] = -1;                  swt[tid] = 0.f; }
    }
    __syncthreads();

    const int warp = tid >> 5;
    const int wm = warp & 1, wn = warp >> 1;

    const int a_r = tid >> 2;
    const int a_c = (tid & 3) << 3;                 // half2 units: 0,8,16,24
    const bool avalid = (m0 + a_r) < n_eff;
    const __half2* ap = g_act + ((size_t)e * CAPE + m0 + a_r) * ID + a_c;

    const int b_r = tid >> 3;                        // 0..31
    const int b_c = (tid & 7) << 3;                  // 0..56 step 8
    const float* bp0 = wdown + (size_t)e * ID * HD + (size_t)b_r * HD + n0 + b_c;

    wmma::fragment<wmma::accumulator, 16, 16, 16, float> c[2];
    wmma::fill_fragment(c[0], 0.f);
    wmma::fill_fragment(c[1], 0.f);

    uint4 va0, va1; float4 rb0, rb1;
    auto load_regs = [&](int k) {
        if (avalid) { va0 = *(const uint4*)(ap + k); va1 = *(const uint4*)(ap + k + 4); }
        else        { va0 = make_uint4(0,0,0,0); va1 = va0; }
        const float* bp = bp0 + (size_t)k * HD;
        rb0 = *(const float4*)(bp); rb1 = *(const float4*)(bp + 4);
    };
    auto store_stage = [&](int s) {
        uint4 uh, ul;
        uh.x = __byte_perm(va0.x, va0.y, 0x5410); ul.x = __byte_perm(va0.x, va0.y, 0x7632);
        uh.y = __byte_perm(va0.z, va0.w, 0x5410); ul.y = __byte_perm(va0.z, va0.w, 0x7632);
        uh.z = __byte_perm(va1.x, va1.y, 0x5410); ul.z = __byte_perm(va1.x, va1.y, 0x7632);
        uh.w = __byte_perm(va1.z, va1.w, 0x5410); ul.w = __byte_perm(va1.z, va1.w, 0x7632);
        *(uint4*)&sAh[s][a_r][a_c] = uh;
        *(uint4*)&sAl[s][a_r][a_c] = ul;
        float fb[8] = {rb0.x, rb0.y, rb0.z, rb0.w, rb1.x, rb1.y, rb1.z, rb1.w};
        *(uint4*)&sB[s][b_r][b_c] = hi8(fb);
    };

    load_regs(0);
    store_stage(0);
    __syncthreads();

    const int NK = ID / 32;
    for (int ks = 0; ks < NK; ks++) {
        const int cur = ks & 1;
        const bool hasnext = (ks + 1 < NK);
        if (hasnext) load_regs((ks + 1) * 32);
#pragma unroll
        for (int sub = 0; sub < 2; sub++) {
            wmma::fragment<wmma::matrix_a, 16, 16, 16, __half, wmma::row_major> a0h, a1h, a0l, a1l;
            wmma::load_matrix_sync(a0h, &sAh[cur][wm * 32][sub * 16], 40);
            wmma::load_matrix_sync(a1h, &sAh[cur][wm * 32 + 16][sub * 16], 40);
            wmma::load_matrix_sync(a0l, &sAl[cur][wm * 32][sub * 16], 40);
            wmma::load_matrix_sync(a1l, &sAl[cur][wm * 32 + 16][sub * 16], 40);
            wmma::fragment<wmma::matrix_b, 16, 16, 16, __half, wmma::row_major> b;
            wmma::load_matrix_sync(b, &sB[cur][sub * 16][wn * 16], 72);
            wmma::mma_sync(c[0], a0h, b, c[0]);
            wmma::mma_sync(c[1], a1h, b, c[1]);
            wmma::mma_sync(c[0], a0l, b, c[0]);
            wmma::mma_sync(c[1], a1l, b, c[1]);
        }
        if (hasnext) store_stage(cur ^ 1);
        __syncthreads();
    }

    float (*sOut)[68] = (float(*)[68])smem_raw;
#pragma unroll
    for (int i = 0; i < 2; i++)
        wmma::store_matrix_sync(&sOut[wm * 32 + i * 16][wn * 16], c[i], 68, wmma::mem_row_major);
    __syncwarp();

    const int lane = tid & 31;
    for (int i = lane; i < 32 * 16; i += 32) {
        int r  = wm * 32 + (i >> 4);
        int cc = wn * 16 + (i & 15);
        int t = stok[r];
        if (t >= 0)
            atomicAdd(&out[(size_t)t * HD + n0 + cc], sOut[r][cc] * swt[r]);
    }
}

// ---------------- launcher ----------------
extern "C" void kernel_launch(void* const* d_in, const int* in_sizes, int n_in,
                              void* d_out, int out_size) {
    (void)in_sizes; (void)n_in; (void)out_size;
    const float* x     = (const float*)d_in[0];
    const float* wcls  = (const float*)d_in[1];
    const float* bias  = (const float*)d_in[2];
    const float* wgu   = (const float*)d_in[3];
    const float* wdown = (const float*)d_in[4];
    float* out = (float*)d_out;

    cudaMemsetAsync(out, 0, (size_t)TT * HD * sizeof(float));
    router_kernel<<<TT, 256>>>(x, wcls);
    route_kernel<<<TT / 256, 256>>>(bias);
    dispatch_kernel<<<NEXP, 1024>>>();
    gemm1_kernel<<<dim3(ID / 64, CAPE / 64, NEXP), 256>>>(x, wgu);
    gemm2_kernel<<<dim3(HD / 64, CAPE / 64, NEXP), 256>>>(wdown, out);
}

// round 11
// speedup vs baseline: 1.0040x; 1.0010x over previous
#include <cuda_runtime.h>
#include <cuda_fp16.h>
#include <mma.h>
#include <math.h>

using namespace nvcuda;

#define TT    2048
#define HD    2048
#define ID    1024
#define NEXP  32
#define NEZ   64
#define TOPKK 8
#define CAPE  1024
#define NSLOT (TT * TOPKK)

// ---------------- scratch (static device allocations) ----------------
__device__ float   g_logits[(size_t)TT * NEZ];
__device__ int     g_slot_eid[NSLOT];
__device__ float   g_slot_w[NSLOT];
__device__ int     g_count[NEXP];
__device__ int     g_tok[NEXP * CAPE];
__device__ float   g_wt[NEXP * CAPE];
__device__ __half2 g_act[(size_t)NEXP * CAPE * ID];   // (hi,lo) packed, 128 MB

union H8 { __half h[8]; uint4 u; };

__device__ __forceinline__ void split8(const float* f, uint4* uh, uint4* ul) {
    H8 hh, ll;
#pragma unroll
    for (int i = 0; i < 8; i++) {
        __half h = __float2half_rn(f[i]);
        hh.h[i] = h;
        ll.h[i] = __float2half_rn(f[i] - __half2float(h));
    }
    *uh = hh.u; *ul = ll.u;
}
__device__ __forceinline__ uint4 hi8(const float* f) {
    H8 hh;
#pragma unroll
    for (int i = 0; i < 8; i++) hh.h[i] = __float2half_rn(f[i]);
    return hh.u;
}

// ---------------- kernel 1: router logits, near-exact fp32 (Kahan) ----------
__global__ __launch_bounds__(256) void router_kernel(const float* __restrict__ x,
                                                     const float* __restrict__ wcls) {
    __shared__ float sx[HD];
    const int t = blockIdx.x;
    for (int i = threadIdx.x; i < HD; i += 256)
        sx[i] = x[(size_t)t * HD + i];
    __syncthreads();

    const int warp = threadIdx.x >> 5;
    const int lane = threadIdx.x & 31;
    for (int e = warp; e < NEZ; e += 8) {
        const float* w = wcls + (size_t)e * HD;
        float s = 0.f, comp = 0.f;
        for (int k = lane; k < HD; k += 32) {
            float p  = __fmul_rn(sx[k], w[k]);
            float y  = __fsub_rn(p, comp);
            float t2 = __fadd_rn(s, y);
            comp     = __fsub_rn(__fsub_rn(t2, s), y);
            s = t2;
        }
#pragma unroll
        for (int off = 16; off; off >>= 1)
            s = __fadd_rn(s, __shfl_xor_sync(0xffffffffu, s, off));
        if (lane == 0) g_logits[(size_t)t * NEZ + e] = s;
    }
}

// ---------------- kernel 2: softmax + top-8, write per-slot tables ----------
__global__ void route_kernel(const float* __restrict__ bias) {
    const int t = blockIdx.x * blockDim.x + threadIdx.x;
    if (t >= TT) return;

    const float* lg = g_logits + (size_t)t * NEZ;
    float sc[NEZ];
    float m = -1e30f;
#pragma unroll
    for (int j = 0; j < NEZ; j++) m = fmaxf(m, lg[j]);
    float s = 0.f;
#pragma unroll
    for (int j = 0; j < NEZ; j++) { sc[j] = expf(lg[j] - m); s += sc[j]; }
    const float invs = 1.f / s;
    float sel[NEZ];
#pragma unroll
    for (int j = 0; j < NEZ; j++) { sc[j] *= invs; sel[j] = sc[j] + bias[j]; }

    int   idx[TOPKK];
    float w[TOPKK];
    float wsum = 0.f;
#pragma unroll
    for (int k = 0; k < TOPKK; k++) {
        float best = -1e30f; int bj = 0;
        for (int j = 0; j < NEZ; j++)
            if (sel[j] > best) { best = sel[j]; bj = j; }
        idx[k] = bj;
        w[k]   = sc[bj];
        wsum  += sc[bj];
        sel[bj] = -1e30f;
    }

    const float inv = 1.5f / (wsum + 1e-20f);
    float zsum = 0.f;
#pragma unroll
    for (int k = 0; k < TOPKK; k++)
        if (idx[k] >= NEXP) zsum += w[k] * inv;
    const float zscale = 1.f + zsum;

#pragma unroll
    for (int k = 0; k < TOPKK; k++) {
        int e = idx[k];
        int slot = t * TOPKK + k;
        if (e < NEXP) {
            g_slot_eid[slot] = e;
            g_slot_w[slot]   = w[k] * inv * zscale;
        } else {
            g_slot_eid[slot] = -1;
            g_slot_w[slot]   = 0.f;
        }
    }
}

// ---------------- kernel 2b: deterministic dispatch (reference drop rule) ----
__global__ __launch_bounds__(1024) void dispatch_kernel() {
    const int e = blockIdx.x;
    __shared__ int warp_cnt[32];
    __shared__ int running_s;
    if (threadIdx.x == 0) running_s = 0;
    __syncthreads();

    const int lane = threadIdx.x & 31;
    const int warp = threadIdx.x >> 5;

    for (int base = 0; base < NSLOT; base += 1024) {
        const int i = base + threadIdx.x;
        const bool f = (g_slot_eid[i] == e);
        const unsigned mball = __ballot_sync(0xffffffffu, f);
        const int wprefix = __popc(mball & ((1u << lane) - 1u));
        if (lane == 0) warp_cnt[warp] = __popc(mball);
        __syncthreads();

        int woff = 0, tot = 0;
#pragma unroll
        for (int w2 = 0; w2 < 32; w2++) {
            int c = warp_cnt[w2];
            if (w2 < warp) woff += c;
            tot += c;
        }
        const int run0 = running_s;
        if (f) {
            int pos = run0 + woff + wprefix;
            if (pos < CAPE) {
                g_tok[e * CAPE + pos] = i / TOPKK;
                g_wt [e * CAPE + pos] = g_slot_w[i];
            }
        }
        __syncthreads();
        if (threadIdx.x == 0) running_s = run0 + tot;
        __syncthreads();
    }
    if (threadIdx.x == 0) g_count[e] = running_s;
}

// ---------------- kernel 3: grouped GEMM1 + SwiGLU (pipelined, 2-term) ------
// A (tokens) split hi/lo exactly; B (weights) fp16-hi only.
#define G1_SAH 0
#define G1_SAL 10240
#define G1_SBG 20480
#define G1_SBU 29696
#define G1_SMEM 38912

__global__ __launch_bounds__(256, 2) void gemm1_kernel(const float* __restrict__ x,
                                                       const float* __restrict__ wgu) {
    const int e     = blockIdx.z;
    const int n_eff = min(g_count[e], CAPE);
    const int m0    = blockIdx.y * 64;
    if (m0 >= n_eff) return;
    const int n0 = blockIdx.x * 64;

    __shared__ __align__(16) unsigned char smem_raw[G1_SMEM];
    __shared__ int stok[64];
    typedef __half (*A_t)[64][40];
    typedef __half (*B_t)[32][72];
    A_t sAh = (A_t)(smem_raw + G1_SAH);
    A_t sAl = (A_t)(smem_raw + G1_SAL);
    B_t sBg = (B_t)(smem_raw + G1_SBG);
    B_t sBu = (B_t)(smem_raw + G1_SBU);

    const int tid = threadIdx.x;
    if (tid < 64) {
        int r = m0 + tid;
        stok[tid] = (r < n_eff) ? g_tok[e * CAPE + r] : -1;
    }
    __syncthreads();

    const float* wg = wgu + (size_t)e * HD * (2 * ID);
    const int warp = tid >> 5;
    const int wm = warp & 1, wn = warp >> 1;

    // loader mappings
    const int a_r = tid >> 2;
    const int a_c = (tid & 3) << 3;                 // 0,8,16,24
    const int atok = stok[a_r];
    const float* aptr = (atok >= 0) ? (x + (size_t)atok * HD + a_c) : nullptr;

    const int b_m = tid >> 7;                        // 0=gate, 1=up
    const int b_r = (tid & 127) >> 2;                // 0..31
    const int b_c = (tid & 3) << 4;                  // 0,16,32,48
    const float* bptr = wg + (size_t)b_r * (2 * ID) + b_m * ID + n0 + b_c;
    B_t sBdst = b_m ? sBu : sBg;

    wmma::fragment<wmma::accumulator, 16, 16, 16, float> cg[2], cu[2];
#pragma unroll
    for (int i = 0; i < 2; i++) { wmma::fill_fragment(cg[i], 0.f); wmma::fill_fragment(cu[i], 0.f); }

    float4 ra0, ra1, rb0, rb1, rb2, rb3;
    auto load_regs = [&](int k) {
        if (aptr) { ra0 = *(const float4*)(aptr + k); ra1 = *(const float4*)(aptr + k + 4); }
        else      { ra0 = make_float4(0.f,0.f,0.f,0.f); ra1 = ra0; }
        const float* bp = bptr + (size_t)k * (2 * ID);
        rb0 = *(const float4*)(bp);     rb1 = *(const float4*)(bp + 4);
        rb2 = *(const float4*)(bp + 8); rb3 = *(const float4*)(bp + 12);
    };
    auto store_stage = [&](int s) {
        float fa[8] = {ra0.x, ra0.y, ra0.z, ra0.w, ra1.x, ra1.y, ra1.z, ra1.w};
        uint4 uh, ul; split8(fa, &uh, &ul);
        *(uint4*)&sAh[s][a_r][a_c] = uh;
        *(uint4*)&sAl[s][a_r][a_c] = ul;
        float fb0[8] = {rb0.x, rb0.y, rb0.z, rb0.w, rb1.x, rb1.y, rb1.z, rb1.w};
        float fb1[8] = {rb2.x, rb2.y, rb2.z, rb2.w, rb3.x, rb3.y, rb3.z, rb3.w};
        *(uint4*)&sBdst[s][b_r][b_c]     = hi8(fb0);
        *(uint4*)&sBdst[s][b_r][b_c + 8] = hi8(fb1);
    };

    load_regs(0);
    store_stage(0);
    __syncthreads();

    const int NK = HD / 32;
    for (int ks = 0; ks < NK; ks++) {
        const int cur = ks & 1;
        const bool hasnext = (ks + 1 < NK);
        if (hasnext) load_regs((ks + 1) * 32);
#pragma unroll
        for (int sub = 0; sub < 2; sub++) {
            wmma::fragment<wmma::matrix_a, 16, 16, 16, __half, wmma::row_major> a0h, a1h, a0l, a1l;
            wmma::load_matrix_sync(a0h, &sAh[cur][wm * 32][sub * 16], 40);
            wmma::load_matrix_sync(a1h, &sAh[cur][wm * 32 + 16][sub * 16], 40);
            wmma::load_matrix_sync(a0l, &sAl[cur][wm * 32][sub * 16], 40);
            wmma::load_matrix_sync(a1l, &sAl[cur][wm * 32 + 16][sub * 16], 40);
            wmma::fragment<wmma::matrix_b, 16, 16, 16, __half, wmma::row_major> b;
            wmma::load_matrix_sync(b, &sBg[cur][sub * 16][wn * 16], 72);
            wmma::mma_sync(cg[0], a0h, b, cg[0]);
            wmma::mma_sync(cg[1], a1h, b, cg[1]);
            wmma::mma_sync(cg[0], a0l, b, cg[0]);
            wmma::mma_sync(cg[1], a1l, b, cg[1]);
            wmma::load_matrix_sync(b, &sBu[cur][sub * 16][wn * 16], 72);
            wmma::mma_sync(cu[0], a0h, b, cu[0]);
            wmma::mma_sync(cu[1], a1h, b, cu[1]);
            wmma::mma_sync(cu[0], a0l, b, cu[0]);
            wmma::mma_sync(cu[1], a1l, b, cu[1]);
        }
        if (hasnext) store_stage(cur ^ 1);
        __syncthreads();
    }

    // ---- epilogue (sOut aliases pipeline smem; safe after final sync) ----
    float (*sOut)[68] = (float(*)[68])smem_raw;
    const int lane = tid & 31;
    float gv[16];
#pragma unroll
    for (int i = 0; i < 2; i++)
        wmma::store_matrix_sync(&sOut[wm * 32 + i * 16][wn * 16], cg[i], 68, wmma::mem_row_major);
    __syncwarp();
#pragma unroll
    for (int it = 0; it < 16; it++) {
        int i = it * 32 + lane;
        gv[it] = sOut[wm * 32 + (i >> 4)][wn * 16 + (i & 15)];
    }
    __syncwarp();
#pragma unroll
    for (int i = 0; i < 2; i++)
        wmma::store_matrix_sync(&sOut[wm * 32 + i * 16][wn * 16], cu[i], 68, wmma::mem_row_major);
    __syncwarp();
#pragma unroll
    for (int it = 0; it < 16; it++) {
        int i = it * 32 + lane;
        int r = wm * 32 + (i >> 4);
        int c = wn * 16 + (i & 15);
        int grow = m0 + r;
        if (grow < n_eff) {
            float g = gv[it];
            float u = sOut[r][c];
            float act = g / (1.f + expf(-g)) * u;
            __half hh = __float2half_rn(act);
            __half hl = __float2half_rn(act - __half2float(hh));
            g_act[((size_t)e * CAPE + grow) * ID + n0 + c] = __halves2half2(hh, hl);
        }
    }
}

// ---------------- kernel 4: grouped GEMM2 + weighted scatter (pipelined) ----
#define G2_SAH 0
#define G2_SAL 10240
#define G2_SB  20480
#define G2_SMEM 29696

__global__ __launch_bounds__(256, 2) void gemm2_kernel(const float* __restrict__ wdown,
                                                       float* __restrict__ out) {
    const int e     = blockIdx.z;
    const int n_eff = min(g_count[e], CAPE);
    const int m0    = blockIdx.y * 64;
    if (m0 >= n_eff) return;
    const int n0 = blockIdx.x * 64;

    __shared__ __align__(16) unsigned char smem_raw[G2_SMEM];
    __shared__ int   stok[64];
    __shared__ float swt[64];
    typedef __half (*A_t)[64][40];
    typedef __half (*B_t)[32][72];
    A_t sAh = (A_t)(smem_raw + G2_SAH);
    A_t sAl = (A_t)(smem_raw + G2_SAL);
    B_t sB  = (B_t)(smem_raw + G2_SB);

    const int tid = threadIdx.x;
    if (tid < 64) {
        int r = m0 + tid;
        if (r < n_eff) { stok[tid] = g_tok[e * CAPE + r]; swt[tid] = g_wt[e * CAPE + r]; }
        else           { stok[tid] = -1;                  swt[tid] = 0.f; }
    }
    __syncthreads();

    const int warp = tid >> 5;
    const int wm = warp & 1, wn = warp >> 1;

    const int a_r = tid >> 2;
    const int a_c = (tid & 3) << 3;                 // half2 units: 0,8,16,24
    const bool avalid = (m0 + a_r) < n_eff;
    const __half2* ap = g_act + ((size_t)e * CAPE + m0 + a_r) * ID + a_c;

    const int b_r = tid >> 3;                        // 0..31
    const int b_c = (tid & 7) << 3;                  // 0..56 step 8
    const float* bp0 = wdown + (size_t)e * ID * HD + (size_t)b_r * HD + n0 + b_c;

    wmma::fragment<wmma::accumulator, 16, 16, 16, float> c[2];
    wmma::fill_fragment(c[0], 0.f);
    wmma::fill_fragment(c[1], 0.f);

    uint4 va0, va1; float4 rb0, rb1;
    auto load_regs = [&](int k) {
        if (avalid) { va0 = *(const uint4*)(ap + k); va1 = *(const uint4*)(ap + k + 4); }
        else        { va0 = make_uint4(0,0,0,0); va1 = va0; }
        const float* bp = bp0 + (size_t)k * HD;
        rb0 = *(const float4*)(bp); rb1 = *(const float4*)(bp + 4);
    };
    auto store_stage = [&](int s) {
        uint4 uh, ul;
        uh.x = __byte_perm(va0.x, va0.y, 0x5410); ul.x = __byte_perm(va0.x, va0.y, 0x7632);
        uh.y = __byte_perm(va0.z, va0.w, 0x5410); ul.y = __byte_perm(va0.z, va0.w, 0x7632);
        uh.z = __byte_perm(va1.x, va1.y, 0x5410); ul.z = __byte_perm(va1.x, va1.y, 0x7632);
        uh.w = __byte_perm(va1.z, va1.w, 0x5410); ul.w = __byte_perm(va1.z, va1.w, 0x7632);
        *(uint4*)&sAh[s][a_r][a_c] = uh;
        *(uint4*)&sAl[s][a_r][a_c] = ul;
        float fb[8] = {rb0.x, rb0.y, rb0.z, rb0.w, rb1.x, rb1.y, rb1.z, rb1.w};
        *(uint4*)&sB[s][b_r][b_c] = hi8(fb);
    };

    load_regs(0);
    store_stage(0);
    __syncthreads();

    const int NK = ID / 32;
    for (int ks = 0; ks < NK; ks++) {
        const int cur = ks & 1;
        const bool hasnext = (ks + 1 < NK);
        if (hasnext) load_regs((ks + 1) * 32);
#pragma unroll
        for (int sub = 0; sub < 2; sub++) {
            wmma::fragment<wmma::matrix_a, 16, 16, 16, __half, wmma::row_major> a0h, a1h, a0l, a1l;
            wmma::load_matrix_sync(a0h, &sAh[cur][wm * 32][sub * 16], 40);
            wmma::load_matrix_sync(a1h, &sAh[cur][wm * 32 + 16][sub * 16], 40);
            wmma::load_matrix_sync(a0l, &sAl[cur][wm * 32][sub * 16], 40);
            wmma::load_matrix_sync(a1l, &sAl[cur][wm * 32 + 16][sub * 16], 40);
            wmma::fragment<wmma::matrix_b, 16, 16, 16, __half, wmma::row_major> b;
            wmma::load_matrix_sync(b, &sB[cur][sub * 16][wn * 16], 72);
            wmma::mma_sync(c[0], a0h, b, c[0]);
            wmma::mma_sync(c[1], a1h, b, c[1]);
            wmma::mma_sync(c[0], a0l, b, c[0]);
            wmma::mma_sync(c[1], a1l, b, c[1]);
        }
        if (hasnext) store_stage(cur ^ 1);
        __syncthreads();
    }

    float (*sOut)[68] = (float(*)[68])smem_raw;
#pragma unroll
    for (int i = 0; i < 2; i++)
        wmma::store_matrix_sync(&sOut[wm * 32 + i * 16][wn * 16], c[i], 68, wmma::mem_row_major);
    __syncwarp();

    const int lane = tid & 31;
    for (int i = lane; i < 32 * 16; i += 32) {
        int r  = wm * 32 + (i >> 4);
        int cc = wn * 16 + (i & 15);
        int t = stok[r];
        if (t >= 0)
            atomicAdd(&out[(size_t)t * HD + n0 + cc], sOut[r][cc] * swt[r]);
    }
}

// ---------------- launcher ----------------
extern "C" void kernel_launch(void* const* d_in, const int* in_sizes, int n_in,
                              void* d_out, int out_size) {
    (void)in_sizes; (void)n_in; (void)out_size;
    const float* x     = (const float*)d_in[0];
    const float* wcls  = (const float*)d_in[1];
    const float* bias  = (const float*)d_in[2];
    const float* wgu   = (const float*)d_in[3];
    const float* wdown = (const float*)d_in[4];
    float* out = (float*)d_out;

    cudaMemsetAsync(out, 0, (size_t)TT * HD * sizeof(float));
    router_kernel<<<TT, 256>>>(x, wcls);
    route_kernel<<<TT / 256, 256>>>(bias);
    dispatch_kernel<<<NEXP, 1024>>>();
    gemm1_kernel<<<dim3(ID / 64, CAPE / 64, NEXP), 256>>>(x, wgu);
    gemm2_kernel<<<dim3(HD / 64, CAPE / 64, NEXP), 256>>>(wdown, out);
}

// round 12
// speedup vs baseline: 1.0044x; 1.0004x over previous
#include <cuda_runtime.h>
#include <cuda_fp16.h>
#include <mma.h>
#include <math.h>

using namespace nvcuda;

#define TT    2048
#define HD    2048
#define ID    1024
#define NEXP  32
#define NEZ   64
#define TOPKK 8
#define CAPE  1024
#define NSLOT (TT * TOPKK)

// ---------------- scratch (static device allocations) ----------------
__device__ float   g_logits[(size_t)TT * NEZ];
__device__ int     g_slot_eid[NSLOT];
__device__ float   g_slot_w[NSLOT];
__device__ int     g_count[NEXP];
__device__ int     g_tok[NEXP * CAPE];
__device__ float   g_wt[NEXP * CAPE];
__device__ __half2 g_act[(size_t)NEXP * CAPE * ID];   // (hi,lo) packed, 128 MB

union H8 { __half h[8]; uint4 u; };

__device__ __forceinline__ void split8(const float* f, uint4* uh, uint4* ul) {
    H8 hh, ll;
#pragma unroll
    for (int i = 0; i < 8; i++) {
        __half h = __float2half_rn(f[i]);
        hh.h[i] = h;
        ll.h[i] = __float2half_rn(f[i] - __half2float(h));
    }
    *uh = hh.u; *ul = ll.u;
}
__device__ __forceinline__ uint4 hi8(const float* f) {
    H8 hh;
#pragma unroll
    for (int i = 0; i < 8; i++) hh.h[i] = __float2half_rn(f[i]);
    return hh.u;
}

// ---------------- kernel 1: router logits, near-exact fp32 (Kahan) ----------
__global__ __launch_bounds__(256) void router_kernel(const float* __restrict__ x,
                                                     const float* __restrict__ wcls) {
    __shared__ float sx[HD];
    const int t = blockIdx.x;
    for (int i = threadIdx.x; i < HD; i += 256)
        sx[i] = x[(size_t)t * HD + i];
    __syncthreads();

    const int warp = threadIdx.x >> 5;
    const int lane = threadIdx.x & 31;
    for (int e = warp; e < NEZ; e += 8) {
        const float* w = wcls + (size_t)e * HD;
        float s = 0.f, comp = 0.f;
        for (int k = lane; k < HD; k += 32) {
            float p  = __fmul_rn(sx[k], w[k]);
            float y  = __fsub_rn(p, comp);
            float t2 = __fadd_rn(s, y);
            comp     = __fsub_rn(__fsub_rn(t2, s), y);
            s = t2;
        }
#pragma unroll
        for (int off = 16; off; off >>= 1)
            s = __fadd_rn(s, __shfl_xor_sync(0xffffffffu, s, off));
        if (lane == 0) g_logits[(size_t)t * NEZ + e] = s;
    }
}

// ---------------- kernel 2: softmax + top-8, write per-slot tables ----------
__global__ void route_kernel(const float* __restrict__ bias) {
    const int t = blockIdx.x * blockDim.x + threadIdx.x;
    if (t >= TT) return;

    const float* lg = g_logits + (size_t)t * NEZ;
    float sc[NEZ];
    float m = -1e30f;
#pragma unroll
    for (int j = 0; j < NEZ; j++) m = fmaxf(m, lg[j]);
    float s = 0.f;
#pragma unroll
    for (int j = 0; j < NEZ; j++) { sc[j] = expf(lg[j] - m); s += sc[j]; }
    const float invs = 1.f / s;
    float sel[NEZ];
#pragma unroll
    for (int j = 0; j < NEZ; j++) { sc[j] *= invs; sel[j] = sc[j] + bias[j]; }

    int   idx[TOPKK];
    float w[TOPKK];
    float wsum = 0.f;
#pragma unroll
    for (int k = 0; k < TOPKK; k++) {
        float best = -1e30f; int bj = 0;
        for (int j = 0; j < NEZ; j++)
            if (sel[j] > best) { best = sel[j]; bj = j; }
        idx[k] = bj;
        w[k]   = sc[bj];
        wsum  += sc[bj];
        sel[bj] = -1e30f;
    }

    const float inv = 1.5f / (wsum + 1e-20f);
    float zsum = 0.f;
#pragma unroll
    for (int k = 0; k < TOPKK; k++)
        if (idx[k] >= NEXP) zsum += w[k] * inv;
    const float zscale = 1.f + zsum;

#pragma unroll
    for (int k = 0; k < TOPKK; k++) {
        int e = idx[k];
        int slot = t * TOPKK + k;
        if (e < NEXP) {
            g_slot_eid[slot] = e;
            g_slot_w[slot]   = w[k] * inv * zscale;
        } else {
            g_slot_eid[slot] = -1;
            g_slot_w[slot]   = 0.f;
        }
    }
}

// ---------------- kernel 2b: deterministic dispatch (reference drop rule) ----
__global__ __launch_bounds__(1024) void dispatch_kernel() {
    const int e = blockIdx.x;
    __shared__ int warp_cnt[32];
    __shared__ int running_s;
    if (threadIdx.x == 0) running_s = 0;
    __syncthreads();

    const int lane = threadIdx.x & 31;
    const int warp = threadIdx.x >> 5;

    for (int base = 0; base < NSLOT; base += 1024) {
        const int i = base + threadIdx.x;
        const bool f = (g_slot_eid[i] == e);
        const unsigned mball = __ballot_sync(0xffffffffu, f);
        const int wprefix = __popc(mball & ((1u << lane) - 1u));
        if (lane == 0) warp_cnt[warp] = __popc(mball);
        __syncthreads();

        int woff = 0, tot = 0;
#pragma unroll
        for (int w2 = 0; w2 < 32; w2++) {
            int c = warp_cnt[w2];
            if (w2 < warp) woff += c;
            tot += c;
        }
        const int run0 = running_s;
        if (f) {
            int pos = run0 + woff + wprefix;
            if (pos < CAPE) {
                g_tok[e * CAPE + pos] = i / TOPKK;
                g_wt [e * CAPE + pos] = g_slot_w[i];
            }
        }
        __syncthreads();
        if (threadIdx.x == 0) running_s = run0 + tot;
        __syncthreads();
    }
    if (threadIdx.x == 0) g_count[e] = running_s;
}

// ---------------- kernel 3: grouped GEMM1 + SwiGLU (pipelined, 2-term) ------
// A (tokens) split hi/lo exactly; B (weights) fp16-hi only.
#define G1_SAH 0
#define G1_SAL 10240
#define G1_SBG 20480
#define G1_SBU 29696
#define G1_SMEM 38912

__global__ __launch_bounds__(256, 2) void gemm1_kernel(const float* __restrict__ x,
                                                       const float* __restrict__ wgu) {
    const int e     = blockIdx.z;
    const int n_eff = min(g_count[e], CAPE);
    const int m0    = blockIdx.y * 64;
    if (m0 >= n_eff) return;
    const int n0 = blockIdx.x * 64;

    __shared__ __align__(16) unsigned char smem_raw[G1_SMEM];
    __shared__ int stok[64];
    typedef __half (*A_t)[64][40];
    typedef __half (*B_t)[32][72];
    A_t sAh = (A_t)(smem_raw + G1_SAH);
    A_t sAl = (A_t)(smem_raw + G1_SAL);
    B_t sBg = (B_t)(smem_raw + G1_SBG);
    B_t sBu = (B_t)(smem_raw + G1_SBU);

    const int tid = threadIdx.x;
    if (tid < 64) {
        int r = m0 + tid;
        stok[tid] = (r < n_eff) ? g_tok[e * CAPE + r] : -1;
    }
    __syncthreads();

    const float* wg = wgu + (size_t)e * HD * (2 * ID);
    const int warp = tid >> 5;
    const int wm = warp & 1, wn = warp >> 1;

    // loader mappings
    const int a_r = tid >> 2;
    const int a_c = (tid & 3) << 3;                 // 0,8,16,24
    const int atok = stok[a_r];
    const float* aptr = (atok >= 0) ? (x + (size_t)atok * HD + a_c) : nullptr;

    const int b_m = tid >> 7;                        // 0=gate, 1=up
    const int b_r = (tid & 127) >> 2;                // 0..31
    const int b_c = (tid & 3) << 4;                  // 0,16,32,48
    const float* bptr = wg + (size_t)b_r * (2 * ID) + b_m * ID + n0 + b_c;
    B_t sBdst = b_m ? sBu : sBg;

    wmma::fragment<wmma::accumulator, 16, 16, 16, float> cg[2], cu[2];
#pragma unroll
    for (int i = 0; i < 2; i++) { wmma::fill_fragment(cg[i], 0.f); wmma::fill_fragment(cu[i], 0.f); }

    float4 ra0, ra1, rb0, rb1, rb2, rb3;
    auto load_regs = [&](int k) {
        if (aptr) { ra0 = *(const float4*)(aptr + k); ra1 = *(const float4*)(aptr + k + 4); }
        else      { ra0 = make_float4(0.f,0.f,0.f,0.f); ra1 = ra0; }
        const float* bp = bptr + (size_t)k * (2 * ID);
        rb0 = *(const float4*)(bp);     rb1 = *(const float4*)(bp + 4);
        rb2 = *(const float4*)(bp + 8); rb3 = *(const float4*)(bp + 12);
    };
    auto store_stage = [&](int s) {
        float fa[8] = {ra0.x, ra0.y, ra0.z, ra0.w, ra1.x, ra1.y, ra1.z, ra1.w};
        uint4 uh, ul; split8(fa, &uh, &ul);
        *(uint4*)&sAh[s][a_r][a_c] = uh;
        *(uint4*)&sAl[s][a_r][a_c] = ul;
        float fb0[8] = {rb0.x, rb0.y, rb0.z, rb0.w, rb1.x, rb1.y, rb1.z, rb1.w};
        float fb1[8] = {rb2.x, rb2.y, rb2.z, rb2.w, rb3.x, rb3.y, rb3.z, rb3.w};
        *(uint4*)&sBdst[s][b_r][b_c]     = hi8(fb0);
        *(uint4*)&sBdst[s][b_r][b_c + 8] = hi8(fb1);
    };

    load_regs(0);
    store_stage(0);
    __syncthreads();

    const int NK = HD / 32;
    for (int ks = 0; ks < NK; ks++) {
        const int cur = ks & 1;
        const bool hasnext = (ks + 1 < NK);
        if (hasnext) load_regs((ks + 1) * 32);
#pragma unroll
        for (int sub = 0; sub < 2; sub++) {
            wmma::fragment<wmma::matrix_a, 16, 16, 16, __half, wmma::row_major> a0h, a1h, a0l, a1l;
            wmma::load_matrix_sync(a0h, &sAh[cur][wm * 32][sub * 16], 40);
            wmma::load_matrix_sync(a1h, &sAh[cur][wm * 32 + 16][sub * 16], 40);
            wmma::load_matrix_sync(a0l, &sAl[cur][wm * 32][sub * 16], 40);
            wmma::load_matrix_sync(a1l, &sAl[cur][wm * 32 + 16][sub * 16], 40);
            wmma::fragment<wmma::matrix_b, 16, 16, 16, __half, wmma::row_major> b;
            wmma::load_matrix_sync(b, &sBg[cur][sub * 16][wn * 16], 72);
            wmma::mma_sync(cg[0], a0h, b, cg[0]);
            wmma::mma_sync(cg[1], a1h, b, cg[1]);
            wmma::mma_sync(cg[0], a0l, b, cg[0]);
            wmma::mma_sync(cg[1], a1l, b, cg[1]);
            wmma::load_matrix_sync(b, &sBu[cur][sub * 16][wn * 16], 72);
            wmma::mma_sync(cu[0], a0h, b, cu[0]);
            wmma::mma_sync(cu[1], a1h, b, cu[1]);
            wmma::mma_sync(cu[0], a0l, b, cu[0]);
            wmma::mma_sync(cu[1], a1l, b, cu[1]);
        }
        if (hasnext) store_stage(cur ^ 1);
        __syncthreads();
    }

    // ---- epilogue (sOut aliases pipeline smem; safe after final sync) ----
    float (*sOut)[68] = (float(*)[68])smem_raw;
    const int lane = tid & 31;
    float gv[16];
#pragma unroll
    for (int i = 0; i < 2; i++)
        wmma::store_matrix_sync(&sOut[wm * 32 + i * 16][wn * 16], cg[i], 68, wmma::mem_row_major);
    __syncwarp();
#pragma unroll
    for (int it = 0; it < 16; it++) {
        int i = it * 32 + lane;
        gv[it] = sOut[wm * 32 + (i >> 4)][wn * 16 + (i & 15)];
    }
    __syncwarp();
#pragma unroll
    for (int i = 0; i < 2; i++)
        wmma::store_matrix_sync(&sOut[wm * 32 + i * 16][wn * 16], cu[i], 68, wmma::mem_row_major);
    __syncwarp();
#pragma unroll
    for (int it = 0; it < 16; it++) {
        int i = it * 32 + lane;
        int r = wm * 32 + (i >> 4);
        int c = wn * 16 + (i & 15);
        int grow = m0 + r;
        if (grow < n_eff) {
            float g = gv[it];
            float u = sOut[r][c];
            float act = g / (1.f + expf(-g)) * u;
            __half hh = __float2half_rn(act);
            __half hl = __float2half_rn(act - __half2float(hh));
            g_act[((size_t)e * CAPE + grow) * ID + n0 + c] = __halves2half2(hh, hl);
        }
    }
}

// ---------------- kernel 4: grouped GEMM2 + weighted scatter (pipelined) ----
#define G2_SAH 0
#define G2_SAL 10240
#define G2_SB  20480
#define G2_SMEM 29696

__global__ __launch_bounds__(256, 2) void gemm2_kernel(const float* __restrict__ wdown,
                                                       float* __restrict__ out) {
    const int e     = blockIdx.z;
    const int n_eff = min(g_count[e], CAPE);
    const int m0    = blockIdx.y * 64;
    if (m0 >= n_eff) return;
    const int n0 = blockIdx.x * 64;

    __shared__ __align__(16) unsigned char smem_raw[G2_SMEM];
    __shared__ int   stok[64];
    __shared__ float swt[64];
    typedef __half (*A_t)[64][40];
    typedef __half (*B_t)[32][72];
    A_t sAh = (A_t)(smem_raw + G2_SAH);
    A_t sAl = (A_t)(smem_raw + G2_SAL);
    B_t sB  = (B_t)(smem_raw + G2_SB);

    const int tid = threadIdx.x;
    if (tid < 64) {
        int r = m0 + tid;
        if (r < n_eff) { stok[tid] = g_tok[e * CAPE + r]; swt[tid] = g_wt[e * CAPE + r]; }
        else           { stok[tid] = -1;                  swt[tid] = 0.f; }
    }
    __syncthreads();

    const int warp = tid >> 5;
    const int wm = warp & 1, wn = warp >> 1;

    const int a_r = tid >> 2;
    const int a_c = (tid & 3) << 3;                 // half2 units: 0,8,16,24
    const bool avalid = (m0 + a_r) < n_eff;
    const __half2* ap = g_act + ((size_t)e * CAPE + m0 + a_r) * ID + a_c;

    const int b_r = tid >> 3;                        // 0..31
    const int b_c = (tid & 7) << 3;                  // 0..56 step 8
    const float* bp0 = wdown + (size_t)e * ID * HD + (size_t)b_r * HD + n0 + b_c;

    wmma::fragment<wmma::accumulator, 16, 16, 16, float> c[2];
    wmma::fill_fragment(c[0], 0.f);
    wmma::fill_fragment(c[1], 0.f);

    uint4 va0, va1; float4 rb0, rb1;
    auto load_regs = [&](int k) {
        if (avalid) { va0 = *(const uint4*)(ap + k); va1 = *(const uint4*)(ap + k + 4); }
        else        { va0 = make_uint4(0,0,0,0); va1 = va0; }
        const float* bp = bp0 + (size_t)k * HD;
        rb0 = *(const float4*)(bp); rb1 = *(const float4*)(bp + 4);
    };
    auto store_stage = [&](int s) {
        uint4 uh, ul;
        uh.x = __byte_perm(va0.x, va0.y, 0x5410); ul.x = __byte_perm(va0.x, va0.y, 0x7632);
        uh.y = __byte_perm(va0.z, va0.w, 0x5410); ul.y = __byte_perm(va0.z, va0.w, 0x7632);
        uh.z = __byte_perm(va1.x, va1.y, 0x5410); ul.z = __byte_perm(va1.x, va1.y, 0x7632);
        uh.w = __byte_perm(va1.z, va1.w, 0x5410); ul.w = __byte_perm(va1.z, va1.w, 0x7632);
        *(uint4*)&sAh[s][a_r][a_c] = uh;
        *(uint4*)&sAl[s][a_r][a_c] = ul;
        float fb[8] = {rb0.x, rb0.y, rb0.z, rb0.w, rb1.x, rb1.y, rb1.z, rb1.w};
        *(uint4*)&sB[s][b_r][b_c] = hi8(fb);
    };

    load_regs(0);
    store_stage(0);
    __syncthreads();

    const int NK = ID / 32;
    for (int ks = 0; ks < NK; ks++) {
        const int cur = ks & 1;
        const bool hasnext = (ks + 1 < NK);
        if (hasnext) load_regs((ks + 1) * 32);
#pragma unroll
        for (int sub = 0; sub < 2; sub++) {
            wmma::fragment<wmma::matrix_a, 16, 16, 16, __half, wmma::row_major> a0h, a1h, a0l, a1l;
            wmma::load_matrix_sync(a0h, &sAh[cur][wm * 32][sub * 16], 40);
            wmma::load_matrix_sync(a1h, &sAh[cur][wm * 32 + 16][sub * 16], 40);
            wmma::load_matrix_sync(a0l, &sAl[cur][wm * 32][sub * 16], 40);
            wmma::load_matrix_sync(a1l, &sAl[cur][wm * 32 + 16][sub * 16], 40);
            wmma::fragment<wmma::matrix_b, 16, 16, 16, __half, wmma::row_major> b;
            wmma::load_matrix_sync(b, &sB[cur][sub * 16][wn * 16], 72);
            wmma::mma_sync(c[0], a0h, b, c[0]);
            wmma::mma_sync(c[1], a1h, b, c[1]);
            wmma::mma_sync(c[0], a0l, b, c[0]);
            wmma::mma_sync(c[1], a1l, b, c[1]);
        }
        if (hasnext) store_stage(cur ^ 1);
        __syncthreads();
    }

    float (*sOut)[68] = (float(*)[68])smem_raw;
#pragma unroll
    for (int i = 0; i < 2; i++)
        wmma::store_matrix_sync(&sOut[wm * 32 + i * 16][wn * 16], c[i], 68, wmma::mem_row_major);
    __syncwarp();

    const int lane = tid & 31;
    for (int i = lane; i < 32 * 16; i += 32) {
        int r  = wm * 32 + (i >> 4);
        int cc = wn * 16 + (i & 15);
        int t = stok[r];
        if (t >= 0)
            atomicAdd(&out[(size_t)t * HD + n0 + cc], sOut[r][cc] * swt[r]);
    }
}

// ---------------- launcher ----------------
extern "C" void kernel_launch(void* const* d_in, const int* in_sizes, int n_in,
                              void* d_out, int out_size) {
    (void)in_sizes; (void)n_in; (void)out_size;
    const float* x     = (const float*)d_in[0];
    const float* wcls  = (const float*)d_in[1];
    const float* bias  = (const float*)d_in[2];
    const float* wgu   = (const float*)d_in[3];
    const float* wdown = (const float*)d_in[4];
    float* out = (float*)d_out;

    cudaMemsetAsync(out, 0, (size_t)TT * HD * sizeof(float));
    router_kernel<<<TT, 256>>>(x, wcls);
    route_kernel<<<TT / 256, 256>>>(bias);
    dispatch_kernel<<<NEXP, 1024>>>();
    gemm1_kernel<<<dim3(ID / 64, CAPE / 64, NEXP), 256>>>(x, wgu);
    gemm2_kernel<<<dim3(HD / 64, CAPE / 64, NEXP), 256>>>(wdown, out);
}